// round 11
// baseline (speedup 1.0000x reference)
#include <cuda_runtime.h>
#include <cuda_bf16.h>
#include <math.h>
#include <stdint.h>

// Problem constants
#define NROWS   8192          // rows per input
#define M_TOT   16384         // 2*NROWS
#define DDIM    128
#define NTILE   128           // M_TOT / 128 tiles per dim
#define NTRI    8256          // NTILE*(NTILE+1)/2
#define E2_CONST 7.3890560989306495f   // exp(2)

// Device scratch (allocation-free rule: __device__ globals)
__device__ __nv_bfloat16 g_Hn[M_TOT * DDIM];   // normalized rows, bf16
__device__ float g_rowsum[M_TOT];
__device__ float g_spos[NROWS];

// ---------------------------------------------------------------------------
// Kernel 1: L2-normalize each row (warp per row) -> bf16; also zero g_rowsum
// ---------------------------------------------------------------------------
__global__ void norm_kernel(const float* __restrict__ h1,
                            const float* __restrict__ h2) {
    int gwarp = (blockIdx.x * blockDim.x + threadIdx.x) >> 5;
    int lane  = threadIdx.x & 31;
    if (gwarp >= M_TOT) return;
    if (lane == 0) g_rowsum[gwarp] = 0.0f;
    const float* src = (gwarp < NROWS) ? (h1 + (size_t)gwarp * DDIM)
                                       : (h2 + (size_t)(gwarp - NROWS) * DDIM);
    float4 v = reinterpret_cast<const float4*>(src)[lane];
    float ss = v.x * v.x + v.y * v.y + v.z * v.z + v.w * v.w;
    #pragma unroll
    for (int off = 16; off > 0; off >>= 1)
        ss += __shfl_xor_sync(0xFFFFFFFFu, ss, off);
    float inv = rsqrtf(fmaxf(ss, 1e-24f));
    v.x *= inv; v.y *= inv; v.z *= inv; v.w *= inv;
    __nv_bfloat162 p0 = __floats2bfloat162_rn(v.x, v.y);
    __nv_bfloat162 p1 = __floats2bfloat162_rn(v.z, v.w);
    __nv_bfloat162* dst = reinterpret_cast<__nv_bfloat162*>(
        g_Hn + (size_t)gwarp * DDIM + lane * 4);
    dst[0] = p0;
    dst[1] = p1;
}

// ---------------------------------------------------------------------------
// Kernel 2: positive-pair cosine similarity, fp32 (warp per pair)
// ---------------------------------------------------------------------------
__global__ void pos_kernel(const float* __restrict__ h1,
                           const float* __restrict__ h2) {
    int gwarp = (blockIdx.x * blockDim.x + threadIdx.x) >> 5;
    int lane  = threadIdx.x & 31;
    if (gwarp >= NROWS) return;
    float4 va = reinterpret_cast<const float4*>(h1 + (size_t)gwarp * DDIM)[lane];
    float4 vb = reinterpret_cast<const float4*>(h2 + (size_t)gwarp * DDIM)[lane];
    float dot = va.x * vb.x + va.y * vb.y + va.z * vb.z + va.w * vb.w;
    float na  = va.x * va.x + va.y * va.y + va.z * va.z + va.w * va.w;
    float nb  = vb.x * vb.x + vb.y * vb.y + vb.z * vb.z + vb.w * vb.w;
    #pragma unroll
    for (int off = 16; off > 0; off >>= 1) {
        dot += __shfl_xor_sync(0xFFFFFFFFu, dot, off);
        na  += __shfl_xor_sync(0xFFFFFFFFu, na, off);
        nb  += __shfl_xor_sync(0xFFFFFFFFu, nb, off);
    }
    if (lane == 0)
        g_spos[gwarp] = dot * rsqrtf(na) * rsqrtf(nb);
}

// ---------------------------------------------------------------------------
// Kernel 3: Gram tile kernel over the LOWER TRIANGLE of tiles only.
// CTA = 128x128 output tile (bm >= bn), full K = 128 staged once (cp.async).
// 8 warps (2x4), warp tile 64x32, mma.sync m16n8k16 bf16->fp32.
// Epilogue: exp(2s); row sums -> rows of bm; col sums -> rows of bn
// (matrix symmetric, exp elementwise => colsum(tile) = rowsum of mirror).
// ---------------------------------------------------------------------------
#define LDAS 136   // 128 + 8 halves skew: row stride 272B -> conflict-free ldmatrix
#define SMEM_DYN (2 * 128 * LDAS * 2)   // As + Bs = 69632 bytes

__device__ __forceinline__ void ldsm_x4(uint32_t& r0, uint32_t& r1,
                                        uint32_t& r2, uint32_t& r3,
                                        uint32_t saddr) {
    asm volatile("ldmatrix.sync.aligned.m8n8.x4.shared.b16 {%0,%1,%2,%3}, [%4];\n"
                 : "=r"(r0), "=r"(r1), "=r"(r2), "=r"(r3) : "r"(saddr));
}
__device__ __forceinline__ void mma16816(float& c0, float& c1, float& c2, float& c3,
                                         uint32_t a0, uint32_t a1, uint32_t a2, uint32_t a3,
                                         uint32_t b0, uint32_t b1) {
    asm volatile(
        "mma.sync.aligned.m16n8k16.row.col.f32.bf16.bf16.f32 "
        "{%0,%1,%2,%3}, {%4,%5,%6,%7}, {%8,%9}, {%0,%1,%2,%3};\n"
        : "+f"(c0), "+f"(c1), "+f"(c2), "+f"(c3)
        : "r"(a0), "r"(a1), "r"(a2), "r"(a3), "r"(b0), "r"(b1));
}
__device__ __forceinline__ void cp_async16(uint32_t saddr, const void* gptr) {
    asm volatile("cp.async.cg.shared.global [%0], [%1], 16;\n"
                 :: "r"(saddr), "l"(gptr));
}

__global__ void __launch_bounds__(256, 2) gram_kernel() {
    extern __shared__ __align__(16) __nv_bfloat16 sdyn[];
    __nv_bfloat16* As = sdyn;                 // [128][LDAS]
    __nv_bfloat16* Bs = sdyn + 128 * LDAS;    // [128][LDAS]
    __shared__ float rowpart[4][128];   // indexed by wn
    __shared__ float colpart[2][128];   // indexed by wm

    const int tid  = threadIdx.x;
    const int lane = tid & 31;
    const int warp = tid >> 5;
    const int wm = warp >> 2;          // 0..1  -> 64-row half
    const int wn = warp & 3;           // 0..3  -> 32-col quarter

    // Decode linear triangle index -> (bm, bn), bn <= bm
    int idx = blockIdx.x;
    int bm = (int)((sqrtf(8.0f * (float)idx + 1.0f) - 1.0f) * 0.5f);
    while ((bm + 1) * (bm + 2) / 2 <= idx) bm++;
    while (bm * (bm + 1) / 2 > idx) bm--;
    int bn = idx - bm * (bm + 1) / 2;
    const bool is_diag = (bm == bn);

    const __nv_bfloat16* __restrict__ Hn = g_Hn;
    uint32_t as_base = (uint32_t)__cvta_generic_to_shared(As);
    uint32_t bs_base = (uint32_t)__cvta_generic_to_shared(Bs);

    // --- one-shot staged load of A (rows of bm) and B (rows of bn), K=128 ---
    // 2048 16B-chunks per matrix; 256 threads x 8 iters, each iter does A+B.
    #pragma unroll
    for (int it = 0; it < 8; it++) {
        int i2 = tid + it * 256;       // 0..2047
        int r  = i2 >> 4;              // row 0..127
        int c  = i2 & 15;              // 16B chunk -> cols c*8..c*8+7
        uint32_t soff = (uint32_t)(r * LDAS + c * 8) * 2;
        cp_async16(as_base + soff,
                   Hn + (size_t)(bm * 128 + r) * DDIM + c * 8);
        cp_async16(bs_base + soff,
                   Hn + (size_t)(bn * 128 + r) * DDIM + c * 8);
    }
    asm volatile("cp.async.commit_group;\n");

    float acc[4][4][4];
    #pragma unroll
    for (int mt = 0; mt < 4; mt++)
        #pragma unroll
        for (int nt = 0; nt < 4; nt++)
            #pragma unroll
            for (int r = 0; r < 4; r++) acc[mt][nt][r] = 0.0f;

    asm volatile("cp.async.wait_group 0;\n" ::: "memory");
    __syncthreads();

    // --- mainloop: 8 K-steps of 16 ---
    #pragma unroll
    for (int ks = 0; ks < 8; ks++) {
        uint32_t a[4][4];
        #pragma unroll
        for (int mt = 0; mt < 4; mt++) {
            int row = wm * 64 + mt * 16 + (lane & 15);
            uint32_t addr = as_base +
                ((row * LDAS + ks * 16 + (lane >> 4) * 8) << 1);
            ldsm_x4(a[mt][0], a[mt][1], a[mt][2], a[mt][3], addr);
        }
        // B: two x4 loads cover nt = {0,1} and {2,3}
        uint32_t b[4][2];
        #pragma unroll
        for (int p = 0; p < 2; p++) {
            int row = wn * 32 + p * 16 + (lane >> 4) * 8 + (lane & 7);
            uint32_t addr = bs_base +
                ((row * LDAS + ks * 16 + ((lane >> 3) & 1) * 8) << 1);
            ldsm_x4(b[2 * p][0], b[2 * p][1], b[2 * p + 1][0], b[2 * p + 1][1],
                    addr);
        }
        #pragma unroll
        for (int mt = 0; mt < 4; mt++)
            #pragma unroll
            for (int nt = 0; nt < 4; nt++)
                mma16816(acc[mt][nt][0], acc[mt][nt][1],
                         acc[mt][nt][2], acc[mt][nt][3],
                         a[mt][0], a[mt][1], a[mt][2], a[mt][3],
                         b[nt][0], b[nt][1]);
    }
    __syncthreads();

    // --- epilogue: e = exp(2s); row sums AND column sums ---
    // acc fragment: row = lane>>2 (+8 for c2/c3), col = 2*(lane&3) + {0,1}
    float cs0[4], cs1[4];
    #pragma unroll
    for (int nt = 0; nt < 4; nt++) { cs0[nt] = 0.0f; cs1[nt] = 0.0f; }

    #pragma unroll
    for (int mt = 0; mt < 4; mt++) {
        float r0 = 0.0f, r1 = 0.0f;
        #pragma unroll
        for (int nt = 0; nt < 4; nt++) {
            float e0 = __expf(2.0f * acc[mt][nt][0]);
            float e1 = __expf(2.0f * acc[mt][nt][1]);
            float e2 = __expf(2.0f * acc[mt][nt][2]);
            float e3 = __expf(2.0f * acc[mt][nt][3]);
            r0 += e0 + e1;
            r1 += e2 + e3;
            cs0[nt] += e0 + e2;
            cs1[nt] += e1 + e3;
        }
        r0 += __shfl_xor_sync(0xFFFFFFFFu, r0, 1);
        r0 += __shfl_xor_sync(0xFFFFFFFFu, r0, 2);
        r1 += __shfl_xor_sync(0xFFFFFFFFu, r1, 1);
        r1 += __shfl_xor_sync(0xFFFFFFFFu, r1, 2);
        if ((lane & 3) == 0) {
            int lrow = wm * 64 + mt * 16 + (lane >> 2);
            rowpart[wn][lrow]     = r0;
            rowpart[wn][lrow + 8] = r1;
        }
    }

    // column sums: reduce over the row dimension (lane>>2) -> shfl 4,8,16
    #pragma unroll
    for (int nt = 0; nt < 4; nt++) {
        float c0 = cs0[nt], c1 = cs1[nt];
        #pragma unroll
        for (int off = 4; off <= 16; off <<= 1) {
            c0 += __shfl_xor_sync(0xFFFFFFFFu, c0, off);
            c1 += __shfl_xor_sync(0xFFFFFFFFu, c1, off);
        }
        if (lane < 4) {
            int col = wn * 32 + nt * 8 + 2 * lane;
            colpart[wm][col]     = c0;
            colpart[wm][col + 1] = c1;
        }
    }
    __syncthreads();

    if (tid < 128) {
        float s = rowpart[0][tid] + rowpart[1][tid] +
                  rowpart[2][tid] + rowpart[3][tid];
        atomicAdd(&g_rowsum[bm * 128 + tid], s);
    } else if (!is_diag) {
        int c = tid - 128;
        float s = colpart[0][c] + colpart[1][c];
        atomicAdd(&g_rowsum[bn * 128 + c], s);
    }
}

// ---------------------------------------------------------------------------
// Kernel 4: final reduction (single block)
// ---------------------------------------------------------------------------
__global__ void reduce_kernel(float* __restrict__ out) {
    __shared__ float sm[1024];
    int tid = threadIdx.x;
    float acc = 0.0f;
    for (int i = tid; i < M_TOT; i += 1024) {
        float denom = g_rowsum[i] - E2_CONST;
        acc += logf(denom) - 2.0f * g_spos[i & (NROWS - 1)];
    }
    sm[tid] = acc;
    __syncthreads();
    for (int s = 512; s > 0; s >>= 1) {
        if (tid < s) sm[tid] += sm[tid + s];
        __syncthreads();
    }
    if (tid == 0) out[0] = sm[0] / (float)M_TOT;
}

// ---------------------------------------------------------------------------
extern "C" void kernel_launch(void* const* d_in, const int* in_sizes, int n_in,
                              void* d_out, int out_size) {
    const float* h1 = (const float*)d_in[0];
    const float* h2 = (const float*)d_in[1];
    float* out = (float*)d_out;

    cudaFuncSetAttribute(gram_kernel,
                         cudaFuncAttributeMaxDynamicSharedMemorySize, SMEM_DYN);

    norm_kernel<<<(M_TOT * 32 + 255) / 256, 256>>>(h1, h2);
    pos_kernel<<<(NROWS * 32 + 255) / 256, 256>>>(h1, h2);

    gram_kernel<<<NTRI, 256, SMEM_DYN>>>();

    reduce_kernel<<<1, 1024>>>(out);
}

// round 12
// speedup vs baseline: 1.1609x; 1.1609x over previous
#include <cuda_runtime.h>
#include <cuda_bf16.h>
#include <math.h>
#include <stdint.h>

// Problem constants
#define NROWS   8192          // rows per input
#define M_TOT   16384         // 2*NROWS
#define DDIM    128
#define NTILE   128           // M_TOT / 128 tiles per dim
#define NTRI    8256          // NTILE*(NTILE+1)/2
#define E2_CONST 7.3890560989306495f   // exp(2)

// Device scratch (allocation-free rule: __device__ globals)
__device__ __nv_bfloat16 g_Hn[M_TOT * DDIM];   // normalized rows, bf16
__device__ float g_rowsum[M_TOT];
__device__ float g_spos[NROWS];

// ---------------------------------------------------------------------------
// Kernel 1: L2-normalize each row (warp per row) -> bf16; also zero g_rowsum
// ---------------------------------------------------------------------------
__global__ void norm_kernel(const float* __restrict__ h1,
                            const float* __restrict__ h2) {
    int gwarp = (blockIdx.x * blockDim.x + threadIdx.x) >> 5;
    int lane  = threadIdx.x & 31;
    if (gwarp >= M_TOT) return;
    if (lane == 0) g_rowsum[gwarp] = 0.0f;
    const float* src = (gwarp < NROWS) ? (h1 + (size_t)gwarp * DDIM)
                                       : (h2 + (size_t)(gwarp - NROWS) * DDIM);
    float4 v = reinterpret_cast<const float4*>(src)[lane];
    float ss = v.x * v.x + v.y * v.y + v.z * v.z + v.w * v.w;
    #pragma unroll
    for (int off = 16; off > 0; off >>= 1)
        ss += __shfl_xor_sync(0xFFFFFFFFu, ss, off);
    float inv = rsqrtf(fmaxf(ss, 1e-24f));
    v.x *= inv; v.y *= inv; v.z *= inv; v.w *= inv;
    __nv_bfloat162 p0 = __floats2bfloat162_rn(v.x, v.y);
    __nv_bfloat162 p1 = __floats2bfloat162_rn(v.z, v.w);
    __nv_bfloat162* dst = reinterpret_cast<__nv_bfloat162*>(
        g_Hn + (size_t)gwarp * DDIM + lane * 4);
    dst[0] = p0;
    dst[1] = p1;
}

// ---------------------------------------------------------------------------
// Kernel 2: positive-pair cosine similarity, fp32 (warp per pair)
// ---------------------------------------------------------------------------
__global__ void pos_kernel(const float* __restrict__ h1,
                           const float* __restrict__ h2) {
    int gwarp = (blockIdx.x * blockDim.x + threadIdx.x) >> 5;
    int lane  = threadIdx.x & 31;
    if (gwarp >= NROWS) return;
    float4 va = reinterpret_cast<const float4*>(h1 + (size_t)gwarp * DDIM)[lane];
    float4 vb = reinterpret_cast<const float4*>(h2 + (size_t)gwarp * DDIM)[lane];
    float dot = va.x * vb.x + va.y * vb.y + va.z * vb.z + va.w * vb.w;
    float na  = va.x * va.x + va.y * va.y + va.z * va.z + va.w * va.w;
    float nb  = vb.x * vb.x + vb.y * vb.y + vb.z * vb.z + vb.w * vb.w;
    #pragma unroll
    for (int off = 16; off > 0; off >>= 1) {
        dot += __shfl_xor_sync(0xFFFFFFFFu, dot, off);
        na  += __shfl_xor_sync(0xFFFFFFFFu, na, off);
        nb  += __shfl_xor_sync(0xFFFFFFFFu, nb, off);
    }
    if (lane == 0)
        g_spos[gwarp] = dot * rsqrtf(na) * rsqrtf(nb);
}

// ---------------------------------------------------------------------------
// Kernel 3: Gram tile kernel over the LOWER TRIANGLE of tiles only.
// CTA = 128x128 output tile (bm >= bn), K = 128 in two 64-wide chunks,
// double-buffered cp.async so chunk1 streams in while chunk0 is in the MMAs.
// 8 warps (2x4), warp tile 64x32, mma.sync m16n8k16 bf16->fp32.
// Epilogue: exp(2s); row sums -> rows of bm; col sums -> rows of bn
// (matrix symmetric, exp elementwise => colsum(tile) = rowsum of mirror).
// ---------------------------------------------------------------------------
#define LDAS 72   // 64 + 8 halves skew -> conflict-free ldmatrix
#define CHUNK_ELEMS (128 * LDAS)                  // bf16 elems per buffer
#define SMEM_DYN (4 * CHUNK_ELEMS * 2)            // A0,A1,B0,B1 = 73728 bytes

__device__ __forceinline__ void ldsm_x4(uint32_t& r0, uint32_t& r1,
                                        uint32_t& r2, uint32_t& r3,
                                        uint32_t saddr) {
    asm volatile("ldmatrix.sync.aligned.m8n8.x4.shared.b16 {%0,%1,%2,%3}, [%4];\n"
                 : "=r"(r0), "=r"(r1), "=r"(r2), "=r"(r3) : "r"(saddr));
}
__device__ __forceinline__ void mma16816(float& c0, float& c1, float& c2, float& c3,
                                         uint32_t a0, uint32_t a1, uint32_t a2, uint32_t a3,
                                         uint32_t b0, uint32_t b1) {
    asm volatile(
        "mma.sync.aligned.m16n8k16.row.col.f32.bf16.bf16.f32 "
        "{%0,%1,%2,%3}, {%4,%5,%6,%7}, {%8,%9}, {%0,%1,%2,%3};\n"
        : "+f"(c0), "+f"(c1), "+f"(c2), "+f"(c3)
        : "r"(a0), "r"(a1), "r"(a2), "r"(a3), "r"(b0), "r"(b1));
}
__device__ __forceinline__ void cp_async16(uint32_t saddr, const void* gptr) {
    asm volatile("cp.async.cg.shared.global [%0], [%1], 16;\n"
                 :: "r"(saddr), "l"(gptr));
}

__global__ void __launch_bounds__(256, 2) gram_kernel() {
    extern __shared__ __align__(16) __nv_bfloat16 sdyn[];
    // buffers: [A0][A1][B0][B1]
    __shared__ float rowpart[4][128];   // indexed by wn
    __shared__ float colpart[2][128];   // indexed by wm

    const int tid  = threadIdx.x;
    const int lane = tid & 31;
    const int warp = tid >> 5;
    const int wm = warp >> 2;          // 0..1  -> 64-row half
    const int wn = warp & 3;           // 0..3  -> 32-col quarter

    // Decode linear triangle index -> (bm, bn), bn <= bm
    int idx = blockIdx.x;
    int bm = (int)((sqrtf(8.0f * (float)idx + 1.0f) - 1.0f) * 0.5f);
    while ((bm + 1) * (bm + 2) / 2 <= idx) bm++;
    while (bm * (bm + 1) / 2 > idx) bm--;
    int bn = idx - bm * (bm + 1) / 2;
    const bool is_diag = (bm == bn);

    const __nv_bfloat16* __restrict__ Hn = g_Hn;
    uint32_t s0 = (uint32_t)__cvta_generic_to_shared(sdyn);
    uint32_t aBuf[2] = { s0,                        s0 + CHUNK_ELEMS * 2 };
    uint32_t bBuf[2] = { s0 + 2 * CHUNK_ELEMS * 2,  s0 + 3 * CHUNK_ELEMS * 2 };

    // --- issue both chunk loads up front, separate commit groups ---
    #pragma unroll
    for (int kc = 0; kc < 2; kc++) {
        #pragma unroll
        for (int it = 0; it < 4; it++) {
            int i2 = tid + it * 256;       // 0..1023
            int r  = i2 >> 3;              // row 0..127
            int c  = i2 & 7;               // 16B chunk -> cols c*8..c*8+7
            uint32_t soff = (uint32_t)(r * LDAS + c * 8) * 2;
            cp_async16(aBuf[kc] + soff,
                       Hn + (size_t)(bm * 128 + r) * DDIM + kc * 64 + c * 8);
            cp_async16(bBuf[kc] + soff,
                       Hn + (size_t)(bn * 128 + r) * DDIM + kc * 64 + c * 8);
        }
        asm volatile("cp.async.commit_group;\n");
    }

    float acc[4][4][4];
    #pragma unroll
    for (int mt = 0; mt < 4; mt++)
        #pragma unroll
        for (int nt = 0; nt < 4; nt++)
            #pragma unroll
            for (int r = 0; r < 4; r++) acc[mt][nt][r] = 0.0f;

    // --- mainloop: chunk kc ready -> 4 K-steps of 16 ---
    #pragma unroll
    for (int kc = 0; kc < 2; kc++) {
        if (kc == 0)
            asm volatile("cp.async.wait_group 1;\n" ::: "memory");
        else
            asm volatile("cp.async.wait_group 0;\n" ::: "memory");
        __syncthreads();

        uint32_t as_base = aBuf[kc];
        uint32_t bs_base = bBuf[kc];

        #pragma unroll
        for (int ks = 0; ks < 4; ks++) {
            uint32_t a[4][4];
            #pragma unroll
            for (int mt = 0; mt < 4; mt++) {
                int row = wm * 64 + mt * 16 + (lane & 15);
                uint32_t addr = as_base +
                    ((row * LDAS + ks * 16 + (lane >> 4) * 8) << 1);
                ldsm_x4(a[mt][0], a[mt][1], a[mt][2], a[mt][3], addr);
            }
            // B: two x4 loads cover nt = {0,1} and {2,3}
            uint32_t b[4][2];
            #pragma unroll
            for (int p = 0; p < 2; p++) {
                int row = wn * 32 + p * 16 + (lane >> 4) * 8 + (lane & 7);
                uint32_t addr = bs_base +
                    ((row * LDAS + ks * 16 + ((lane >> 3) & 1) * 8) << 1);
                ldsm_x4(b[2 * p][0], b[2 * p][1],
                        b[2 * p + 1][0], b[2 * p + 1][1], addr);
            }
            #pragma unroll
            for (int mt = 0; mt < 4; mt++)
                #pragma unroll
                for (int nt = 0; nt < 4; nt++)
                    mma16816(acc[mt][nt][0], acc[mt][nt][1],
                             acc[mt][nt][2], acc[mt][nt][3],
                             a[mt][0], a[mt][1], a[mt][2], a[mt][3],
                             b[nt][0], b[nt][1]);
        }
    }

    // --- epilogue: e = exp(2s); row sums AND column sums (no sync needed:
    // rowpart/colpart are written fresh below, then one barrier before read) ---
    float cs0[4], cs1[4];
    #pragma unroll
    for (int nt = 0; nt < 4; nt++) { cs0[nt] = 0.0f; cs1[nt] = 0.0f; }

    #pragma unroll
    for (int mt = 0; mt < 4; mt++) {
        float r0 = 0.0f, r1 = 0.0f;
        #pragma unroll
        for (int nt = 0; nt < 4; nt++) {
            float e0 = __expf(2.0f * acc[mt][nt][0]);
            float e1 = __expf(2.0f * acc[mt][nt][1]);
            float e2 = __expf(2.0f * acc[mt][nt][2]);
            float e3 = __expf(2.0f * acc[mt][nt][3]);
            r0 += e0 + e1;
            r1 += e2 + e3;
            cs0[nt] += e0 + e2;
            cs1[nt] += e1 + e3;
        }
        r0 += __shfl_xor_sync(0xFFFFFFFFu, r0, 1);
        r0 += __shfl_xor_sync(0xFFFFFFFFu, r0, 2);
        r1 += __shfl_xor_sync(0xFFFFFFFFu, r1, 1);
        r1 += __shfl_xor_sync(0xFFFFFFFFu, r1, 2);
        if ((lane & 3) == 0) {
            int lrow = wm * 64 + mt * 16 + (lane >> 2);
            rowpart[wn][lrow]     = r0;
            rowpart[wn][lrow + 8] = r1;
        }
    }

    // column sums: reduce over the row dimension (lane>>2) -> shfl 4,8,16
    #pragma unroll
    for (int nt = 0; nt < 4; nt++) {
        float c0 = cs0[nt], c1 = cs1[nt];
        #pragma unroll
        for (int off = 4; off <= 16; off <<= 1) {
            c0 += __shfl_xor_sync(0xFFFFFFFFu, c0, off);
            c1 += __shfl_xor_sync(0xFFFFFFFFu, c1, off);
        }
        if (lane < 4) {
            int col = wn * 32 + nt * 8 + 2 * lane;
            colpart[wm][col]     = c0;
            colpart[wm][col + 1] = c1;
        }
    }
    __syncthreads();

    if (tid < 128) {
        float s = rowpart[0][tid] + rowpart[1][tid] +
                  rowpart[2][tid] + rowpart[3][tid];
        atomicAdd(&g_rowsum[bm * 128 + tid], s);
    } else if (!is_diag) {
        int c = tid - 128;
        float s = colpart[0][c] + colpart[1][c];
        atomicAdd(&g_rowsum[bn * 128 + c], s);
    }
}

// ---------------------------------------------------------------------------
// Kernel 4: final reduction (single block, fast __logf)
// ---------------------------------------------------------------------------
__global__ void reduce_kernel(float* __restrict__ out) {
    __shared__ float sm[1024];
    int tid = threadIdx.x;
    float acc = 0.0f;
    #pragma unroll 4
    for (int i = tid; i < M_TOT; i += 1024) {
        float denom = g_rowsum[i] - E2_CONST;
        acc += __logf(denom) - 2.0f * g_spos[i & (NROWS - 1)];
    }
    sm[tid] = acc;
    __syncthreads();
    for (int s = 512; s > 0; s >>= 1) {
        if (tid < s) sm[tid] += sm[tid + s];
        __syncthreads();
    }
    if (tid == 0) out[0] = sm[0] / (float)M_TOT;
}

// ---------------------------------------------------------------------------
extern "C" void kernel_launch(void* const* d_in, const int* in_sizes, int n_in,
                              void* d_out, int out_size) {
    const float* h1 = (const float*)d_in[0];
    const float* h2 = (const float*)d_in[1];
    float* out = (float*)d_out;

    cudaFuncSetAttribute(gram_kernel,
                         cudaFuncAttributeMaxDynamicSharedMemorySize, SMEM_DYN);

    norm_kernel<<<(M_TOT * 32 + 255) / 256, 256>>>(h1, h2);
    pos_kernel<<<(NROWS * 32 + 255) / 256, 256>>>(h1, h2);

    gram_kernel<<<NTRI, 256, SMEM_DYN>>>();

    reduce_kernel<<<1, 1024>>>(out);
}